// round 10
// baseline (speedup 1.0000x reference)
#include <cuda_runtime.h>
#include <cstdint>

// YoloLoss: input/target (256, 25, 64, 64) f32 -> scalar f32.
// Row i = (b, y, x). Element (i, c) at base(b) + c*4096 + (i & 4095).
// CTA covers 1024 consecutive rows (4 per thread, float4).
//
// Channels 0-4 (box): direct LDG.128 front-batch (R6 path).
// Channels 5-24 (class): cp.async.bulk producer-consumer pipeline:
//   thread 0 streams 4KB p-plane + 4KB t-plane per stage into a 5-stage
//   smem ring with mbarrier complete_tx; all threads consume via LDS.128.
//   The bulk engine keeps DRAM saturated independent of compute stalls.
// Tail: per-block fp32 partial -> i64 fixed point (x2^30, exact via double)
// -> atomicAdd(u64) => bit-deterministic; last block writes out + resets.

#define NROWS    (256 * 64 * 64)     // 1,048,576
#define THREADS  256
#define ROWS_CTA (THREADS * 4)       // 1024
#define BLOCKS   (NROWS / ROWS_CTA)  // 1024

#define NSTAGE   5
#define LOOKAHEAD 4
#define NPLANES  20                  // channels 5..24
#define PLANE_FLOATS 1024
#define STAGE_BYTES  (2 * PLANE_FLOATS * 4)   // 8192 (p + t plane)

#define COORD_W 5.0f
#define NOOBJ_W 0.5f
#define INV_BLOCKS (1.0f / 64.0f)
#define FP_SCALE 1073741824.0        // 2^30

__device__ unsigned long long g_sum;        // zero-init; reset by finisher
__device__ unsigned int       g_done_count; // zero-init; reset by finisher

__device__ __forceinline__ uint32_t smem_u32(const void* p) {
    uint32_t a;
    asm("{ .reg .u64 t; cvta.to.shared.u64 t, %1; cvt.u32.u64 %0, t; }"
        : "=r"(a) : "l"(p));
    return a;
}

__device__ __forceinline__ void mbar_init(uint32_t mbar, uint32_t count) {
    asm volatile("mbarrier.init.shared.b64 [%0], %1;" :: "r"(mbar), "r"(count) : "memory");
}
__device__ __forceinline__ void mbar_arrive(uint32_t mbar) {
    asm volatile("mbarrier.arrive.shared.b64 _, [%0];" :: "r"(mbar) : "memory");
}
__device__ __forceinline__ void mbar_expect_tx(uint32_t mbar, uint32_t bytes) {
    asm volatile("mbarrier.arrive.expect_tx.shared.b64 _, [%0], %1;"
                 :: "r"(mbar), "r"(bytes) : "memory");
}
__device__ __forceinline__ void mbar_wait(uint32_t mbar, uint32_t parity) {
    asm volatile(
        "{\n\t.reg .pred P;\n\t"
        "W_%=:\n\t"
        "mbarrier.try_wait.parity.shared::cta.b64 P, [%0], %1;\n\t"
        "@!P bra W_%=;\n\t"
        "}" :: "r"(mbar), "r"(parity) : "memory");
}
__device__ __forceinline__ void bulk_copy_g2s(uint32_t dst_smem, const void* src,
                                              uint32_t bytes, uint32_t mbar) {
    asm volatile(
        "cp.async.bulk.shared::cta.global.mbarrier::complete_tx::bytes "
        "[%0], [%1], %2, [%3];"
        :: "r"(dst_smem), "l"(src), "r"(bytes), "r"(mbar) : "memory");
}

__global__ void __launch_bounds__(THREADS, 4) yolo_loss_fused(
    const float* __restrict__ inp, const float* __restrict__ tgt,
    float* __restrict__ out)
{
    __shared__ alignas(128) float splanes[NSTAGE][2][PLANE_FLOATS];  // 40KB
    __shared__ alignas(8) unsigned long long full_bar[NSTAGE];
    __shared__ alignas(8) unsigned long long empty_bar[NSTAGE];
    __shared__ float ws[THREADS / 32];

    const int tid  = threadIdx.x;
    const int i0c  = blockIdx.x * ROWS_CTA;   // first row of CTA tile
    const int b    = i0c >> 12;               // / 4096 (1024 | 4096: no straddle)
    const int offc = i0c & 4095;
    const float* __restrict__ pbase = inp + (size_t)b * (25 * 4096) + offc;
    const float* __restrict__ tbase = tgt + (size_t)b * (25 * 4096) + offc;

    // ---- pipeline init ----
    uint32_t full_a[NSTAGE], empty_a[NSTAGE];
#pragma unroll
    for (int s = 0; s < NSTAGE; s++) {
        full_a[s]  = smem_u32(&full_bar[s]);
        empty_a[s] = smem_u32(&empty_bar[s]);
    }
    if (tid == 0) {
#pragma unroll
        for (int s = 0; s < NSTAGE; s++) {
            mbar_init(full_a[s], 1);          // expect_tx arrive
            mbar_init(empty_a[s], THREADS);   // all consumers arrive
        }
    }
    __syncthreads();

    // ---- prologue: issue first LOOKAHEAD class-plane stage copies ----
    if (tid == 0) {
#pragma unroll
        for (int j = 0; j < LOOKAHEAD; j++) {
            const int s = j;                              // j < NSTAGE
            // empty parity for issue j: 1 ^ ((j/NSTAGE)&1); j<NSTAGE -> 1 (passes)
            mbar_wait(empty_a[s], 1u);
            mbar_expect_tx(full_a[s], STAGE_BYTES);
            const int c = 5 + j;
            bulk_copy_g2s(smem_u32(&splanes[s][0][0]), pbase + c * 4096,
                          PLANE_FLOATS * 4, full_a[s]);
            bulk_copy_g2s(smem_u32(&splanes[s][1][0]), tbase + c * 4096,
                          PLANE_FLOATS * 4, full_a[s]);
        }
    }

    // ---- box channels 0-4: direct LDG.128 (overlaps with TMA prologue) ----
    const float* __restrict__ pb = pbase + tid * 4;
    const float* __restrict__ tb = tbase + tid * 4;

    float P[5][4], T[5][4];
#pragma unroll
    for (int c = 0; c < 5; c++) {
        float4 pv = *reinterpret_cast<const float4*>(pb + c * 4096);
        float4 tv = *reinterpret_cast<const float4*>(tb + c * 4096);
        P[c][0] = pv.x; P[c][1] = pv.y; P[c][2] = pv.z; P[c][3] = pv.w;
        T[c][0] = tv.x; T[c][1] = tv.y; T[c][2] = tv.z; T[c][3] = tv.w;
    }

    float m[4];
    float lsum = 0.0f;

#pragma unroll
    for (int l = 0; l < 4; l++) {
        const float p0 = P[0][l], p1 = P[1][l], p2 = P[2][l], p3 = P[3][l], p4 = P[4][l];
        const float t0 = T[0][l], t1 = T[1][l], t2 = T[2][l], t3 = T[3][l], t4 = T[4][l];

        const float mm = (t4 > 0.0f) ? 1.0f : 0.0f;
        m[l] = mm;

        const float c1x = p0 * INV_BLOCKS, c1y = p1 * INV_BLOCKS;
        const float c2x = t0 * INV_BLOCKS, c2y = t1 * INV_BLOCKS;
        const float x1a = c1x - 0.5f * p2, x2a = c1x + 0.5f * p2;
        const float y1a = c1y - 0.5f * p3, y2a = c1y + 0.5f * p3;
        const float x1b = c2x - 0.5f * t2, x2b = c2x + 0.5f * t2;
        const float y1b = c2y - 0.5f * t3, y2b = c2y + 0.5f * t3;
        const float dx = fminf(x2a, x2b) - fmaxf(x1a, x1b);
        const float dy = fminf(y2a, y2b) - fmaxf(y1a, y1b);
        const float inter = dx * dy;
        const float uni   = p2 * p3 + t2 * t3 - inter;
        const bool  pos   = (dx > 0.0f) && (dy > 0.0f);
        const float iou   = pos ? (inter / uni) : 0.0f;

        const float sp2 = sqrtf(p2), sp3 = sqrtf(p3);
        const float st2 = sqrtf(t2), st3 = sqrtf(t3);

        const float dxy = (p0 - t0) * (p0 - t0) + (p1 - t1) * (p1 - t1);
        const float dwh = (sp2 - st2) * (sp2 - st2) + (sp3 - st3) * (sp3 - st3);
        const float dcf = (p4 - iou) * (p4 - iou);
        const float dnb = p4 * p4;

        lsum += mm * (COORD_W * (dxy + dwh) + dcf)
              + NOOBJ_W * (1.0f - mm) * dnb;
    }

    // ---- class channels 5-24: consume the smem pipeline ----
#pragma unroll 1
    for (int k = 0; k < NPLANES; k++) {
        const int s = k % NSTAGE;
        const uint32_t cons_parity = (uint32_t)((k / NSTAGE) & 1);
        mbar_wait(full_a[s], cons_parity);

        float4 pv = *reinterpret_cast<const float4*>(&splanes[s][0][tid * 4]);
        float4 tv = *reinterpret_cast<const float4*>(&splanes[s][1][tid * 4]);
        float d0 = pv.x - tv.x, d1 = pv.y - tv.y, d2 = pv.z - tv.z, d3 = pv.w - tv.w;
        lsum += m[0] * d0 * d0 + m[1] * d1 * d1 + m[2] * d2 * d2 + m[3] * d3 * d3;

        mbar_arrive(empty_a[s]);

        if (tid == 0) {
            const int j = k + LOOKAHEAD;
            if (j < NPLANES) {
                const int sj = j % NSTAGE;
                const uint32_t prod_parity = 1u ^ (uint32_t)((j / NSTAGE) & 1);
                mbar_wait(empty_a[sj], prod_parity);
                mbar_expect_tx(full_a[sj], STAGE_BYTES);
                const int c = 5 + j;
                bulk_copy_g2s(smem_u32(&splanes[sj][0][0]), pbase + c * 4096,
                              PLANE_FLOATS * 4, full_a[sj]);
                bulk_copy_g2s(smem_u32(&splanes[sj][1][0]), tbase + c * 4096,
                              PLANE_FLOATS * 4, full_a[sj]);
            }
        }
    }

    // ---- warp + block reduce, fixed-point atomic tail ----
#pragma unroll
    for (int o = 16; o > 0; o >>= 1)
        lsum += __shfl_xor_sync(0xFFFFFFFFu, lsum, o);

    const int lane = tid & 31;
    const int warp = tid >> 5;
    if (lane == 0) ws[warp] = lsum;
    __syncthreads();

    if (tid == 0) {
        float v = 0.0f;
#pragma unroll
        for (int w = 0; w < THREADS / 32; w++) v += ws[w];

        long long q = __double2ll_rn((double)v * FP_SCALE);
        atomicAdd(&g_sum, (unsigned long long)q);   // order-independent
        __threadfence();
        unsigned int prev = atomicAdd(&g_done_count, 1u);
        if (prev == BLOCKS - 1) {
            unsigned long long total = atomicAdd(&g_sum, 0ULL);
            out[0] = (float)((double)(long long)total * (1.0 / FP_SCALE));
            g_done_count = 0;   // reset for next graph replay
            g_sum = 0ULL;
            __threadfence();
        }
    }
}

extern "C" void kernel_launch(void* const* d_in, const int* in_sizes, int n_in,
                              void* d_out, int out_size)
{
    const float* inp = (const float*)d_in[0];
    const float* tgt = (const float*)d_in[1];
    float* out = (float*)d_out;

    yolo_loss_fused<<<BLOCKS, THREADS>>>(inp, tgt, out);
}

// round 11
// speedup vs baseline: 1.1157x; 1.1157x over previous
#include <cuda_runtime.h>

// YoloLoss: input/target (256, 25, 64, 64) f32 -> scalar f32.
// Row i = (b, y, x). Element (i, c) at base(b) + c*4096 + (i & 4095).
// Each thread handles 4 consecutive rows (one float4 per channel).
//
// Load-order restructure of R6: masks first (t4,p4 only), then the 20-channel
// class streaming loop with ~30 live regs (deep load batching), then the
// remaining 8 box vectors + dependency-heavy box math at the END where its
// latency blocks no further load issue. __fdividef for the iou division.
// Tail: per-block fp32 partial -> i64 fixed point (x2^30, exact via double)
// -> atomicAdd(u64) => bit-deterministic; last block writes out + resets.

#define NROWS   (256 * 64 * 64)      // 1,048,576
#define GROUPS  (NROWS / 4)          // 262,144
#define THREADS 256
#define BLOCKS  (GROUPS / THREADS)   // 1024

#define COORD_W 5.0f
#define NOOBJ_W 0.5f
#define INV_BLOCKS (1.0f / 64.0f)
#define FP_SCALE 1073741824.0        // 2^30

__device__ unsigned long long g_sum;        // zero-init; reset by finisher
__device__ unsigned int       g_done_count; // zero-init; reset by finisher

__global__ void __launch_bounds__(THREADS, 4) yolo_loss_fused(
    const float* __restrict__ inp, const float* __restrict__ tgt,
    float* __restrict__ out)
{
    const int gid = blockIdx.x * THREADS + threadIdx.x;
    const int i0  = gid << 2;                 // first of 4 rows
    const int b   = i0 >> 12;                 // / 4096
    const int off = i0 & 4095;
    const float* __restrict__ pb = inp + (size_t)b * (25 * 4096) + off;
    const float* __restrict__ tb = tgt + (size_t)b * (25 * 4096) + off;

    // ---- Phase 1: confidence channels -> masks (minimal live state) ----
    float4 p4v = *reinterpret_cast<const float4*>(pb + 4 * 4096);
    float4 t4v = *reinterpret_cast<const float4*>(tb + 4 * 4096);
    float p4[4] = {p4v.x, p4v.y, p4v.z, p4v.w};
    float m[4];
    m[0] = (t4v.x > 0.0f) ? 1.0f : 0.0f;
    m[1] = (t4v.y > 0.0f) ? 1.0f : 0.0f;
    m[2] = (t4v.z > 0.0f) ? 1.0f : 0.0f;
    m[3] = (t4v.w > 0.0f) ? 1.0f : 0.0f;

    float lsum = 0.0f;

    // ---- Phase 2: class channels 5..24 — pure streaming, masks ready ----
#pragma unroll
    for (int c = 5; c < 25; c++) {
        float4 pv = *reinterpret_cast<const float4*>(pb + c * 4096);
        float4 tv = *reinterpret_cast<const float4*>(tb + c * 4096);
        float d0 = pv.x - tv.x, d1 = pv.y - tv.y, d2 = pv.z - tv.z, d3 = pv.w - tv.w;
        lsum += m[0] * d0 * d0 + m[1] * d1 * d1 + m[2] * d2 * d2 + m[3] * d3 * d3;
    }

    // ---- Phase 3: box channels 0..3 + math at the end ----
    float P[4][4], T[4][4];
#pragma unroll
    for (int c = 0; c < 4; c++) {
        float4 pv = *reinterpret_cast<const float4*>(pb + c * 4096);
        float4 tv = *reinterpret_cast<const float4*>(tb + c * 4096);
        P[c][0] = pv.x; P[c][1] = pv.y; P[c][2] = pv.z; P[c][3] = pv.w;
        T[c][0] = tv.x; T[c][1] = tv.y; T[c][2] = tv.z; T[c][3] = tv.w;
    }

#pragma unroll
    for (int l = 0; l < 4; l++) {
        const float p0 = P[0][l], p1 = P[1][l], p2 = P[2][l], p3 = P[3][l];
        const float t0 = T[0][l], t1 = T[1][l], t2 = T[2][l], t3 = T[3][l];
        const float mm = m[l], pc = p4[l];

        const float c1x = p0 * INV_BLOCKS, c1y = p1 * INV_BLOCKS;
        const float c2x = t0 * INV_BLOCKS, c2y = t1 * INV_BLOCKS;
        const float x1a = c1x - 0.5f * p2, x2a = c1x + 0.5f * p2;
        const float y1a = c1y - 0.5f * p3, y2a = c1y + 0.5f * p3;
        const float x1b = c2x - 0.5f * t2, x2b = c2x + 0.5f * t2;
        const float y1b = c2y - 0.5f * t3, y2b = c2y + 0.5f * t3;
        const float dx = fminf(x2a, x2b) - fmaxf(x1a, x1b);
        const float dy = fminf(y2a, y2b) - fmaxf(y1a, y1b);
        const float inter = dx * dy;
        const float uni   = p2 * p3 + t2 * t3 - inter;
        const bool  pos   = (dx > 0.0f) && (dy > 0.0f);
        const float iou   = pos ? __fdividef(inter, uni) : 0.0f;

        const float sp2 = sqrtf(p2), sp3 = sqrtf(p3);
        const float st2 = sqrtf(t2), st3 = sqrtf(t3);

        const float dxy = (p0 - t0) * (p0 - t0) + (p1 - t1) * (p1 - t1);
        const float dwh = (sp2 - st2) * (sp2 - st2) + (sp3 - st3) * (sp3 - st3);
        const float dcf = (pc - iou) * (pc - iou);
        const float dnb = pc * pc;

        lsum += mm * (COORD_W * (dxy + dwh) + dcf)
              + NOOBJ_W * (1.0f - mm) * dnb;
    }

    // ---- warp + block reduce, fixed-point atomic tail ----
#pragma unroll
    for (int o = 16; o > 0; o >>= 1)
        lsum += __shfl_xor_sync(0xFFFFFFFFu, lsum, o);

    __shared__ float ws[THREADS / 32];
    const int lane = threadIdx.x & 31;
    const int warp = threadIdx.x >> 5;
    if (lane == 0) ws[warp] = lsum;
    __syncthreads();

    if (threadIdx.x == 0) {
        float v = 0.0f;
#pragma unroll
        for (int w = 0; w < THREADS / 32; w++) v += ws[w];

        long long q = __double2ll_rn((double)v * FP_SCALE);
        atomicAdd(&g_sum, (unsigned long long)q);   // order-independent
        __threadfence();
        unsigned int prev = atomicAdd(&g_done_count, 1u);
        if (prev == BLOCKS - 1) {
            unsigned long long total = atomicAdd(&g_sum, 0ULL);
            out[0] = (float)((double)(long long)total * (1.0 / FP_SCALE));
            g_done_count = 0;   // reset for next graph replay
            g_sum = 0ULL;
            __threadfence();
        }
    }
}

extern "C" void kernel_launch(void* const* d_in, const int* in_sizes, int n_in,
                              void* d_out, int out_size)
{
    const float* inp = (const float*)d_in[0];
    const float* tgt = (const float*)d_in[1];
    float* out = (float*)d_out;

    yolo_loss_fused<<<BLOCKS, THREADS>>>(inp, tgt, out);
}

// round 12
// speedup vs baseline: 1.1565x; 1.0366x over previous
#include <cuda_runtime.h>

// YoloLoss: input/target (256, 25, 64, 64) f32 -> scalar f32.
// Row i = (b, y, x). Element (i, c) at base(b) + c*4096 + (i & 4095).
// Each thread handles 4 consecutive rows (one float4 per channel).
//
// R6 structure (best), but WITHOUT the 4-CTA register cap: the lightweight
// tail should compile naturally to <=64 regs (R1-like schedule) without
// ptxas re-scheduling the streaming loop under artificial pressure.
// Tail: per-block fp32 partial -> i64 fixed point (x2^30, exact via double)
// -> atomicAdd(u64) => bit-deterministic; last block writes out + resets.

#define NROWS   (256 * 64 * 64)      // 1,048,576
#define GROUPS  (NROWS / 4)          // 262,144
#define THREADS 256
#define BLOCKS  (GROUPS / THREADS)   // 1024

#define COORD_W 5.0f
#define NOOBJ_W 0.5f
#define INV_BLOCKS (1.0f / 64.0f)
#define FP_SCALE 1073741824.0        // 2^30

__device__ unsigned long long g_sum;        // zero-init; reset by finisher
__device__ unsigned int       g_done_count; // zero-init; reset by finisher

__global__ void __launch_bounds__(THREADS) yolo_loss_fused(
    const float* __restrict__ inp, const float* __restrict__ tgt,
    float* __restrict__ out)
{
    const int gid = blockIdx.x * THREADS + threadIdx.x;
    const int i0  = gid << 2;                 // first of 4 rows
    const int b   = i0 >> 12;                 // / 4096
    const int off = i0 & 4095;
    const float* __restrict__ pb = inp + (size_t)b * (25 * 4096) + off;
    const float* __restrict__ tb = tgt + (size_t)b * (25 * 4096) + off;

    // Front-batched loads of the 5 box channels (10x LDG.128).
    float P[5][4], T[5][4];
#pragma unroll
    for (int c = 0; c < 5; c++) {
        float4 pv = *reinterpret_cast<const float4*>(pb + c * 4096);
        float4 tv = *reinterpret_cast<const float4*>(tb + c * 4096);
        P[c][0] = pv.x; P[c][1] = pv.y; P[c][2] = pv.z; P[c][3] = pv.w;
        T[c][0] = tv.x; T[c][1] = tv.y; T[c][2] = tv.z; T[c][3] = tv.w;
    }

    float m[4];
    float lsum = 0.0f;

#pragma unroll
    for (int l = 0; l < 4; l++) {
        const float p0 = P[0][l], p1 = P[1][l], p2 = P[2][l], p3 = P[3][l], p4 = P[4][l];
        const float t0 = T[0][l], t1 = T[1][l], t2 = T[2][l], t3 = T[3][l], t4 = T[4][l];

        const float mm = (t4 > 0.0f) ? 1.0f : 0.0f;
        m[l] = mm;

        const float c1x = p0 * INV_BLOCKS, c1y = p1 * INV_BLOCKS;
        const float c2x = t0 * INV_BLOCKS, c2y = t1 * INV_BLOCKS;
        const float x1a = c1x - 0.5f * p2, x2a = c1x + 0.5f * p2;
        const float y1a = c1y - 0.5f * p3, y2a = c1y + 0.5f * p3;
        const float x1b = c2x - 0.5f * t2, x2b = c2x + 0.5f * t2;
        const float y1b = c2y - 0.5f * t3, y2b = c2y + 0.5f * t3;
        const float dx = fminf(x2a, x2b) - fmaxf(x1a, x1b);
        const float dy = fminf(y2a, y2b) - fmaxf(y1a, y1b);
        const float inter = dx * dy;
        const float uni   = p2 * p3 + t2 * t3 - inter;
        const bool  pos   = (dx > 0.0f) && (dy > 0.0f);
        const float iou   = pos ? (inter / uni) : 0.0f;

        const float sp2 = sqrtf(p2), sp3 = sqrtf(p3);
        const float st2 = sqrtf(t2), st3 = sqrtf(t3);

        const float dxy = (p0 - t0) * (p0 - t0) + (p1 - t1) * (p1 - t1);
        const float dwh = (sp2 - st2) * (sp2 - st2) + (sp3 - st3) * (sp3 - st3);
        const float dcf = (p4 - iou) * (p4 - iou);
        const float dnb = p4 * p4;

        lsum += mm * (COORD_W * (dxy + dwh) + dcf)
              + NOOBJ_W * (1.0f - mm) * dnb;
    }

    // Class channels 5..24: streamed float4 loads.
#pragma unroll
    for (int c = 5; c < 25; c++) {
        float4 pv = *reinterpret_cast<const float4*>(pb + c * 4096);
        float4 tv = *reinterpret_cast<const float4*>(tb + c * 4096);
        float d0 = pv.x - tv.x, d1 = pv.y - tv.y, d2 = pv.z - tv.z, d3 = pv.w - tv.w;
        lsum += m[0] * d0 * d0 + m[1] * d1 * d1 + m[2] * d2 * d2 + m[3] * d3 * d3;
    }

    // Warp reduce.
#pragma unroll
    for (int o = 16; o > 0; o >>= 1)
        lsum += __shfl_xor_sync(0xFFFFFFFFu, lsum, o);

    __shared__ float ws[THREADS / 32];
    const int lane = threadIdx.x & 31;
    const int warp = threadIdx.x >> 5;
    if (lane == 0) ws[warp] = lsum;
    __syncthreads();

    if (threadIdx.x == 0) {
        float v = 0.0f;
#pragma unroll
        for (int w = 0; w < THREADS / 32; w++) v += ws[w];

        long long q = __double2ll_rn((double)v * FP_SCALE);
        atomicAdd(&g_sum, (unsigned long long)q);   // order-independent
        __threadfence();
        unsigned int prev = atomicAdd(&g_done_count, 1u);
        if (prev == BLOCKS - 1) {
            unsigned long long total = atomicAdd(&g_sum, 0ULL);
            out[0] = (float)((double)(long long)total * (1.0 / FP_SCALE));
            g_done_count = 0;   // reset for next graph replay
            g_sum = 0ULL;
            __threadfence();
        }
    }
}

extern "C" void kernel_launch(void* const* d_in, const int* in_sizes, int n_in,
                              void* d_out, int out_size)
{
    const float* inp = (const float*)d_in[0];
    const float* tgt = (const float*)d_in[1];
    float* out = (float*)d_out;

    yolo_loss_fused<<<BLOCKS, THREADS>>>(inp, tgt, out);
}